// round 6
// baseline (speedup 1.0000x reference)
#include <cuda_runtime.h>
#include <cuda_bf16.h>
#include <cstdint>
#include <cstddef>

// Problem constants
#define BB   64
#define TT   2048
#define DD   256
#define HH   256
#define OO   256
#define FH   1024   // 4*H

// Phase-2 partitioning: 16 clusters x 8 CTAs. Cluster = 4 batches.
// CTA (cluster cid, rank r): hidden units [r*32, r*32+32) for those 4 batches.
#define CL   8      // CTAs per cluster
#define GB   4      // batches per cluster
#define HU   32     // hidden units per CTA
#define NC   128    // gate columns per CTA (4*HU)

// Device-global scratch (allocation-free per harness rules)
__device__ float g_G[(size_t)BB * TT * FH];    // 536 MB: x@Wih + bh
__device__ float g_Hall[(size_t)BB * TT * HH]; // 134 MB: every h_t

// ---------------------------------------------------------------------------
// fp32 GEMM: C[M,N] = A[M,K] @ B[K,N] + bias[N]
// 128x128 tile, 256 threads, 8x8 micro-tile, K-chunks of 16.
// ---------------------------------------------------------------------------
__global__ __launch_bounds__(256, 2) void gemm_kernel(
    const float* __restrict__ A, const float* __restrict__ B,
    const float* __restrict__ bias, float* __restrict__ C,
    int M, int N, int K)
{
    __shared__ float As[16][132];   // A tile transposed: [k][row], padded
    __shared__ float Bs[16][132];   // B tile: [k][col], padded

    const int tid  = threadIdx.x;
    const int m0   = blockIdx.y * 128;
    const int n0   = blockIdx.x * 128;
    const int ty   = tid >> 4, tx = tid & 15;
    const int arow = tid >> 1, aseg = (tid & 1) * 8;
    const int brow = tid >> 4, bcol = (tid & 15) * 4;

    float acc[8][8];
#pragma unroll
    for (int i = 0; i < 8; i++)
#pragma unroll
        for (int j = 0; j < 8; j++) acc[i][j] = 0.f;

    for (int k0 = 0; k0 < K; k0 += 16) {
        float4 av0 = *(const float4*)&A[(size_t)(m0 + arow) * K + k0 + aseg];
        float4 av1 = *(const float4*)&A[(size_t)(m0 + arow) * K + k0 + aseg + 4];
        float4 bv0 = *(const float4*)&B[(size_t)(k0 + brow) * N + n0 + bcol];
        float4 bv1 = *(const float4*)&B[(size_t)(k0 + brow) * N + n0 + bcol + 64];

        As[aseg + 0][arow] = av0.x; As[aseg + 1][arow] = av0.y;
        As[aseg + 2][arow] = av0.z; As[aseg + 3][arow] = av0.w;
        As[aseg + 4][arow] = av1.x; As[aseg + 5][arow] = av1.y;
        As[aseg + 6][arow] = av1.z; As[aseg + 7][arow] = av1.w;
        *(float4*)&Bs[brow][bcol]      = bv0;
        *(float4*)&Bs[brow][bcol + 64] = bv1;
        __syncthreads();

#pragma unroll
        for (int k = 0; k < 16; k++) {
            float a[8], b[8];
            *(float4*)&a[0] = *(const float4*)&As[k][ty * 8];
            *(float4*)&a[4] = *(const float4*)&As[k][ty * 8 + 4];
            *(float4*)&b[0] = *(const float4*)&Bs[k][tx * 8];
            *(float4*)&b[4] = *(const float4*)&Bs[k][tx * 8 + 4];
#pragma unroll
            for (int i = 0; i < 8; i++)
#pragma unroll
                for (int j = 0; j < 8; j++)
                    acc[i][j] = fmaf(a[i], b[j], acc[i][j]);
        }
        __syncthreads();
    }

#pragma unroll
    for (int i = 0; i < 8; i++) {
        size_t row = (size_t)(m0 + ty * 8 + i);
#pragma unroll
        for (int j = 0; j < 8; j += 4) {
            int col = n0 + tx * 8 + j;
            float4 v;
            v.x = acc[i][j + 0] + bias[col + 0];
            v.y = acc[i][j + 1] + bias[col + 1];
            v.z = acc[i][j + 2] + bias[col + 2];
            v.w = acc[i][j + 3] + bias[col + 3];
            *(float4*)&C[row * N + col] = v;
        }
    }
}

// ---------------------------------------------------------------------------
// PTX helpers for the cluster recurrence
// ---------------------------------------------------------------------------
__device__ __forceinline__ uint32_t smem_u32(const void* p) {
    uint32_t a;
    asm("{ .reg .u64 t; cvta.to.shared.u64 t, %1; cvt.u32.u64 %0, t; }"
        : "=r"(a) : "l"(p));
    return a;
}

__device__ __forceinline__ void mbar_init(uint32_t addr, uint32_t count) {
    asm volatile("mbarrier.init.shared.b64 [%0], %1;" :: "r"(addr), "r"(count) : "memory");
}

// Release-arrive (cluster scope) on the mbarrier at the same SMEM offset in
// CTA `rank` of this cluster.
__device__ __forceinline__ void mbar_arrive_cluster(uint32_t local_addr, uint32_t rank) {
    asm volatile(
        "{\n\t"
        ".reg .b32 ra;\n\t"
        "mapa.shared::cluster.u32 ra, %0, %1;\n\t"
        "mbarrier.arrive.release.cluster.shared::cluster.b64 _, [ra];\n\t"
        "}"
        :: "r"(local_addr), "r"(rank) : "memory");
}

// Acquire-wait (cluster scope) on local mbarrier, phase parity `par`.
__device__ __forceinline__ void mbar_wait_cluster(uint32_t addr, uint32_t par) {
    asm volatile(
        "{\n\t"
        ".reg .pred P;\n\t"
        "WL_%=:\n\t"
        "mbarrier.try_wait.parity.acquire.cluster.shared::cta.b64 P, [%0], %1, 0x989680;\n\t"
        "@P bra.uni WD_%=;\n\t"
        "bra.uni WL_%=;\n\t"
        "WD_%=:\n\t"
        "}"
        :: "r"(addr), "r"(par) : "memory");
}

__device__ __forceinline__ void st_cluster_f32(uint32_t local_addr, uint32_t rank, float v) {
    asm volatile(
        "{\n\t"
        ".reg .b32 ra;\n\t"
        "mapa.shared::cluster.u32 ra, %0, %1;\n\t"
        "st.shared::cluster.f32 [ra], %2;\n\t"
        "}"
        :: "r"(local_addr), "r"(rank), "f"(v) : "memory");
}

__device__ __forceinline__ float sigm(float x) {
    return 1.f / (1.f + __expf(-x));
}
__device__ __forceinline__ float tanhe(float x) {
    // tanh(x) = 1 - 2/(e^{2x}+1); saturates correctly at +-inf. ~1e-6 rel err.
    return 1.f - 2.f / (__expf(2.f * x) + 1.f);
}

// ---------------------------------------------------------------------------
// Phase 2: persistent LSTM recurrence, cluster version.
// grid = 128 CTAs as 16 clusters of 8. Cluster cid owns batches
// [cid*4, cid*4+4); rank r owns hidden units [r*32, r*32+32).
// Thread layout (GEMV): half = tid>>7 (k in [half*128, half*128+128)),
//   c = tid&127 (gate col: gate = c>>5, u = c&31, global col gate*256+r*32+u).
//   w[128] registers = Whh k-slice of that column.
// Per step: GEMV partials -> smem reduce -> 128 pointwise threads update
//   (c,h), scatter h directly into all 8 CTAs' double-buffered h SMEM via
//   DSMEM, release-arrive on every CTA's mbarrier, acquire-wait, repeat.
// ---------------------------------------------------------------------------
__global__ __launch_bounds__(256, 1) __cluster_dims__(CL, 1, 1)
void lstm_kernel(const float* __restrict__ c0, const float* __restrict__ h0,
                 const float* __restrict__ Whh)
{
    const int cid  = blockIdx.x / CL;
    uint32_t rr;
    asm("mov.u32 %0, %%cluster_ctarank;" : "=r"(rr));
    const int r    = (int)rr;
    const int tid  = threadIdx.x;
    const int half = tid >> 7;          // 0..1 (k-half)
    const int c    = tid & 127;         // 0..127 (gate col)
    const int gate = c >> 5, u = c & 31;
    const int gcol = gate * 256 + r * HU + u;

    __shared__ float hbuf[2][GB][HH];   // 8 KB double-buffered h
    __shared__ float red[2][GB][NC];    // 4 KB k-half partials
    __shared__ alignas(8) unsigned long long mbar_storage;

    const uint32_t mbar = smem_u32(&mbar_storage);

    // One-time: Whh column slice into registers (full unroll -> const indices)
    float w[128];
#pragma unroll
    for (int i = 0; i < 128; i++)
        w[i] = Whh[(size_t)(half * 128 + i) * FH + gcol];

    // h0 into buffer 0 (local loads only; every CTA loads its 4 batches)
    for (int idx = tid; idx < GB * HH; idx += 256) {
        int b = idx >> 8, k = idx & 255;
        hbuf[0][b][k] = h0[(size_t)(cid * GB + b) * HH + k];
    }

    // Pointwise-thread state
    float creg = 0.f;
    int pb = 0, pu = 0;
    size_t gbase = 0, hallbase = 0;
    if (tid < 128) {
        pb = tid >> 5; pu = tid & 31;
        creg = c0[(size_t)(cid * GB + pb) * HH + r * HU + pu];
        gbase    = ((size_t)(cid * GB + pb) * TT) * FH + r * HU + pu;
        hallbase = ((size_t)(cid * GB + pb) * TT) * HH + r * HU + pu;
    }

    if (tid == 0) mbar_init(mbar, CL);
    __syncthreads();
    // All cluster CTAs' mbarriers must be live before any remote arrive.
    asm volatile("barrier.cluster.arrive.aligned;" ::: "memory");
    asm volatile("barrier.cluster.wait.aligned;" ::: "memory");

    for (int t = 0; t < TT; t++) {
        const int cur = t & 1, nxt = cur ^ 1;

        // Prefetch this step's x@Wih+bh contributions (DRAM, consumed late)
        float pgi = 0.f, pgf = 0.f, pgg = 0.f, pgo = 0.f;
        if (tid < 128) {
            const float* gp = &g_G[gbase + (size_t)t * FH];
            pgi = gp[0]; pgf = gp[256]; pgg = gp[512]; pgo = gp[768];
        }

        // GEMV partials over my k-half for all 4 batches (broadcast LDS)
        {
            const float4* h0p = (const float4*)&hbuf[cur][0][half * 128];
            const float4* h1p = (const float4*)&hbuf[cur][1][half * 128];
            const float4* h2p = (const float4*)&hbuf[cur][2][half * 128];
            const float4* h3p = (const float4*)&hbuf[cur][3][half * 128];
            float a0 = 0.f, a1 = 0.f, a2 = 0.f, a3 = 0.f;
#pragma unroll
            for (int i = 0; i < 32; i++) {
                float4 v0 = h0p[i], v1 = h1p[i], v2 = h2p[i], v3 = h3p[i];
                a0 = fmaf(v0.x, w[4*i+0], a0); a0 = fmaf(v0.y, w[4*i+1], a0);
                a0 = fmaf(v0.z, w[4*i+2], a0); a0 = fmaf(v0.w, w[4*i+3], a0);
                a1 = fmaf(v1.x, w[4*i+0], a1); a1 = fmaf(v1.y, w[4*i+1], a1);
                a1 = fmaf(v1.z, w[4*i+2], a1); a1 = fmaf(v1.w, w[4*i+3], a1);
                a2 = fmaf(v2.x, w[4*i+0], a2); a2 = fmaf(v2.y, w[4*i+1], a2);
                a2 = fmaf(v2.z, w[4*i+2], a2); a2 = fmaf(v2.w, w[4*i+3], a2);
                a3 = fmaf(v3.x, w[4*i+0], a3); a3 = fmaf(v3.y, w[4*i+1], a3);
                a3 = fmaf(v3.z, w[4*i+2], a3); a3 = fmaf(v3.w, w[4*i+3], a3);
            }
            red[half][0][c] = a0;
            red[half][1][c] = a1;
            red[half][2][c] = a2;
            red[half][3][c] = a3;
        }
        __syncthreads();

        // Reduce k-halves + LSTM cell + scatter h to all 8 cluster CTAs
        if (tid < 128) {
            float vi = pgi + red[0][pb][pu]      + red[1][pb][pu];
            float vf = pgf + red[0][pb][32 + pu] + red[1][pb][32 + pu];
            float vg = pgg + red[0][pb][64 + pu] + red[1][pb][64 + pu];
            float vo = pgo + red[0][pb][96 + pu] + red[1][pb][96 + pu];

            float ig = sigm(vi);
            float fg = sigm(vf);
            float gg = tanhe(vg);
            float og = sigm(vo);

            creg = fg * creg + ig * gg;
            float hh = og * tanhe(creg);

            // For phase 3 (consumed after kernel completes)
            g_Hall[hallbase + (size_t)t * HH] = hh;

            // DSMEM scatter into next buffer of every cluster CTA (incl self)
            uint32_t la = smem_u32(&hbuf[nxt][pb][r * HU + pu]);
#pragma unroll
            for (uint32_t p = 0; p < CL; p++)
                st_cluster_f32(la, p, hh);
        }
        __syncthreads();   // all scatters happen-before the release-arrives

        if (tid < CL) mbar_arrive_cluster(mbar, (uint32_t)tid);

        mbar_wait_cluster(mbar, (uint32_t)(t & 1));  // acquire: h_t visible
    }
}

// ---------------------------------------------------------------------------
// Launch: G = x@Wih + bh -> LSTM recurrence -> Y = Hall@Wout + bout
// Inputs (metadata order): x, c0, h0, Wih, Whh, bh, Wout, bout
// ---------------------------------------------------------------------------
extern "C" void kernel_launch(void* const* d_in, const int* in_sizes, int n_in,
                              void* d_out, int out_size)
{
    const float* x    = (const float*)d_in[0];
    const float* c0   = (const float*)d_in[1];
    const float* h0   = (const float*)d_in[2];
    const float* Wih  = (const float*)d_in[3];
    const float* Whh  = (const float*)d_in[4];
    const float* bh   = (const float*)d_in[5];
    const float* Wout = (const float*)d_in[6];
    const float* bout = (const float*)d_in[7];
    float* Y = (float*)d_out;

    float* Gp = nullptr;
    float* Hp = nullptr;
    cudaGetSymbolAddress((void**)&Gp, g_G);
    cudaGetSymbolAddress((void**)&Hp, g_Hall);

    // Phase 1: G[B*T, 4H] = x[B*T, D] @ Wih[D, 4H] + bh
    {
        dim3 grid(FH / 128, (BB * TT) / 128);
        gemm_kernel<<<grid, 256>>>(x, Wih, bh, Gp, BB * TT, FH, DD);
    }

    // Phase 2: sequential LSTM over T steps (16 clusters x 8 CTAs)
    lstm_kernel<<<(BB / GB) * CL, 256>>>(c0, h0, Whh);

    // Phase 3: Y[B*T, O] = Hall[B*T, H] @ Wout[H, O] + bout
    {
        dim3 grid(OO / 128, (BB * TT) / 128);
        gemm_kernel<<<grid, 256>>>(Hp, Wout, bout, Y, BB * TT, OO, HH);
    }
}